// round 8
// baseline (speedup 1.0000x reference)
#include <cuda_runtime.h>
#include <cuda_bf16.h>

// LightGCNConv R8: R7 pipeline + warp-per-node gather.
//   CAP=32 == warp width: lane l loads bucket[node*32+l] once (one coalesced
//   LDG for the whole index line) and its nsrc once; the edge loop broadcasts
//   them via __shfl_sync. 1 LDG + 2 SHFL + 2 FMA per edge-iteration, zero
//   warp imbalance (one node per warp), lane owns float2 #l of the row.
//
// Pipeline (4 launches, no memset):
//  1) zero  2) bin (1 edge/thread)  3) norm  4) gather

#define MAX_NODES 100000
#define DFEAT 64
#define F2VEC 32  // float2s per row
#define CAP 32    // bucket row = 128B line = warp width; P(deg>32) ~ 4e-9
#define OVF_MAX 4096

__device__ int   g_outdeg[MAX_NODES];
__device__ int   g_cursor[MAX_NODES];          // becomes in-degree
__device__ float g_nsrc[MAX_NODES];
__device__ float g_ndst[MAX_NODES];
__device__ int   g_bucket[MAX_NODES * CAP];    // 12.8 MB scratch
__device__ int   g_ovf_src[OVF_MAX];
__device__ int   g_ovf_dst[OVF_MAX];
__device__ int   g_ovf_count;

__global__ void zero_kernel(int n) {
    int i = blockIdx.x * blockDim.x + threadIdx.x;
    if (i < n) {
        g_outdeg[i] = 0;
        g_cursor[i] = 0;
    }
    if (i == 0) g_ovf_count = 0;
}

__global__ void bin_kernel(const int* __restrict__ src,
                           const int* __restrict__ dst, int E) {
    int e = blockIdx.x * blockDim.x + threadIdx.x;
    if (e >= E) return;
    int s = src[e];
    int d = dst[e];
    atomicAdd(&g_outdeg[s], 1);                // result unused -> RED
    int slot = atomicAdd(&g_cursor[d], 1);
    if (slot < CAP) {
        g_bucket[d * CAP + slot] = s;
    } else {
        int pos = atomicAdd(&g_ovf_count, 1);
        if (pos < OVF_MAX) {
            g_ovf_src[pos] = s;
            g_ovf_dst[pos] = d;
        }
    }
}

__global__ void norm_kernel(int n) {
    int i = blockIdx.x * blockDim.x + threadIdx.x;
    if (i < n) {
        g_nsrc[i] = rsqrtf((float)max(g_outdeg[i], 1));
        g_ndst[i] = rsqrtf((float)max(g_cursor[i], 1));
    }
}

// One warp per node. Lane l owns float2 #l (64 floats = 32 float2).
__global__ void gather_kernel(const float2* __restrict__ feat2,
                              float2* __restrict__ out2, int N) {
    unsigned gt = blockIdx.x * blockDim.x + threadIdx.x;
    unsigned node = gt >> 5;
    unsigned lane = gt & 31u;
    if (node >= (unsigned)N) return;

    int deg = __ldg(&g_cursor[node]);
    int k = min(deg, CAP);

    // Whole bucket row in one coalesced 128B load; register-resident after.
    int idx = __ldg(&g_bucket[node * CAP + lane]);
    float rn_l = (lane < (unsigned)k) ? __ldg(&g_nsrc[idx]) : 0.f;

    float2 acc = make_float2(0.f, 0.f);

    #pragma unroll 4
    for (int i = 0; i < k; i++) {
        int s   = __shfl_sync(0xffffffffu, idx, i);
        float r = __shfl_sync(0xffffffffu, rn_l, i);
        float2 v = __ldg(&feat2[(unsigned)s * F2VEC + lane]);
        acc.x = fmaf(v.x, r, acc.x);
        acc.y = fmaf(v.y, r, acc.y);
    }

    // Slow path: edges that overflowed this node's bucket (expected: none).
    if (deg > CAP) {
        int ovfn = min(g_ovf_count, OVF_MAX);
        for (int j = 0; j < ovfn; j++) {
            if (g_ovf_dst[j] == (int)node) {
                int s = g_ovf_src[j];
                float r = __ldg(&g_nsrc[s]);
                float2 v = __ldg(&feat2[(unsigned)s * F2VEC + lane]);
                acc.x = fmaf(v.x, r, acc.x);
                acc.y = fmaf(v.y, r, acc.y);
            }
        }
    }

    float nd = __ldg(&g_ndst[node]);
    acc.x *= nd;
    acc.y *= nd;
    out2[(unsigned)node * F2VEC + lane] = acc;
}

extern "C" void kernel_launch(void* const* d_in, const int* in_sizes, int n_in,
                              void* d_out, int out_size) {
    const float2* feat2 = (const float2*)d_in[0];
    const int*    src   = (const int*)d_in[1];
    const int*    dst   = (const int*)d_in[2];
    float2*       out2  = (float2*)d_out;

    int N = in_sizes[0] / DFEAT;   // 100000
    int E = in_sizes[1];           // 1000000

    // 1) zero scratch
    {
        int threads = 256;
        int blocks = (N + threads - 1) / threads;
        zero_kernel<<<blocks, threads>>>(N);
    }

    // 2) degree count + dst binning
    {
        int threads = 256;
        int blocks = (E + threads - 1) / threads;
        bin_kernel<<<blocks, threads>>>(src, dst, E);
    }

    // 3) per-node norms
    {
        int threads = 256;
        int blocks = (N + threads - 1) / threads;
        norm_kernel<<<blocks, threads>>>(N);
    }

    // 4) warp-per-node gather, one write per output element
    {
        long long total = (long long)N * 32;   // one warp (32 threads) per node
        int threads = 256;
        int blocks = (int)((total + threads - 1) / threads);
        gather_kernel<<<blocks, threads>>>(feat2, out2, N);
    }
}

// round 9
// speedup vs baseline: 1.0491x; 1.0491x over previous
#include <cuda_runtime.h>
#include <cuda_bf16.h>

// LightGCNConv R9: R7 pipeline (measured 47.9us) with smem-staged gather.
//   Block = 256 threads = 16 nodes. Prologue stages the 16 bucket rows
//   (indices) and their nsrc values into shared memory; the edge loop is then
//   2 LDS + 1 feat LDG.128 + 4 FMA per iteration (was 3 LDG + 4 FMA).
//
// Pipeline (4 launches, no memset):
//  1) zero  2) bin (1 edge/thread)  3) norm  4) gather

#define MAX_NODES 100000
#define DFEAT 64
#define DVEC 16   // float4s per row
#define CAP 32    // bucket row = 128B line; P(deg>32) ~ 4e-9
#define OVF_MAX 4096
#define NODES_PER_BLK 16

__device__ int   g_outdeg[MAX_NODES];
__device__ int   g_cursor[MAX_NODES];          // becomes in-degree
__device__ float g_nsrc[MAX_NODES];
__device__ float g_ndst[MAX_NODES];
__device__ int   g_bucket[MAX_NODES * CAP];    // 12.8 MB scratch
__device__ int   g_ovf_src[OVF_MAX];
__device__ int   g_ovf_dst[OVF_MAX];
__device__ int   g_ovf_count;

__global__ void zero_kernel(int n) {
    int i = blockIdx.x * blockDim.x + threadIdx.x;
    if (i < n) {
        g_outdeg[i] = 0;
        g_cursor[i] = 0;
    }
    if (i == 0) g_ovf_count = 0;
}

__global__ void bin_kernel(const int* __restrict__ src,
                           const int* __restrict__ dst, int E) {
    int e = blockIdx.x * blockDim.x + threadIdx.x;
    if (e >= E) return;
    int s = src[e];
    int d = dst[e];
    atomicAdd(&g_outdeg[s], 1);                // result unused -> RED
    int slot = atomicAdd(&g_cursor[d], 1);
    if (slot < CAP) {
        g_bucket[d * CAP + slot] = s;
    } else {
        int pos = atomicAdd(&g_ovf_count, 1);
        if (pos < OVF_MAX) {
            g_ovf_src[pos] = s;
            g_ovf_dst[pos] = d;
        }
    }
}

__global__ void norm_kernel(int n) {
    int i = blockIdx.x * blockDim.x + threadIdx.x;
    if (i < n) {
        g_nsrc[i] = rsqrtf((float)max(g_outdeg[i], 1));
        g_ndst[i] = rsqrtf((float)max(g_cursor[i], 1));
    }
}

// 16 lanes per node, 16 nodes per 256-thread block.
// Stage bucket indices + nsrc in smem; loop = 2 LDS + 1 LDG.128 + 4 FMA.
__global__ void gather_kernel(const float4* __restrict__ feat,
                              float4* __restrict__ out, int N) {
    __shared__ int   s_idx[NODES_PER_BLK * CAP];   // 2 KB
    __shared__ float s_rn [NODES_PER_BLK * CAP];   // 2 KB
    __shared__ int   s_deg[NODES_PER_BLK];

    int tid = threadIdx.x;
    int node0 = blockIdx.x * NODES_PER_BLK;

    if (tid < NODES_PER_BLK) {
        int n = node0 + tid;
        s_deg[tid] = (n < N) ? __ldg(&g_cursor[n]) : 0;
    }
    __syncthreads();

    // Stage indices (coalesced) + norms (gather), 2 entries per thread.
    #pragma unroll
    for (int j = tid; j < NODES_PER_BLK * CAP; j += 256) {
        int ln = j >> 5;                 // local node
        int sl = j & 31;                 // slot
        int k  = min(s_deg[ln], CAP);
        if (sl < k) {
            int v = __ldg(&g_bucket[(node0 + ln) * CAP + sl]);
            s_idx[j] = v;
            s_rn[j]  = __ldg(&g_nsrc[v]);
        }
    }
    __syncthreads();

    int ln   = tid >> 4;
    int q    = tid & 15;
    int node = node0 + ln;
    if (node >= N) return;

    int deg = s_deg[ln];
    int k = min(deg, CAP);

    float4 acc = make_float4(0.f, 0.f, 0.f, 0.f);
    const int*   bi = &s_idx[ln * CAP];
    const float* br = &s_rn [ln * CAP];

    #pragma unroll 4
    for (int i = 0; i < k; i++) {
        int s   = bi[i];                 // LDS broadcast within 16-lane group
        float r = br[i];                 // LDS broadcast
        float4 v = __ldg(&feat[(unsigned)s * DVEC + q]);
        acc.x = fmaf(v.x, r, acc.x);
        acc.y = fmaf(v.y, r, acc.y);
        acc.z = fmaf(v.z, r, acc.z);
        acc.w = fmaf(v.w, r, acc.w);
    }

    // Slow path: edges that overflowed this node's bucket (expected: none).
    if (deg > CAP) {
        int ovfn = min(g_ovf_count, OVF_MAX);
        for (int j = 0; j < ovfn; j++) {
            if (g_ovf_dst[j] == node) {
                int s = g_ovf_src[j];
                float r = __ldg(&g_nsrc[s]);
                float4 v = __ldg(&feat[(unsigned)s * DVEC + q]);
                acc.x = fmaf(v.x, r, acc.x);
                acc.y = fmaf(v.y, r, acc.y);
                acc.z = fmaf(v.z, r, acc.z);
                acc.w = fmaf(v.w, r, acc.w);
            }
        }
    }

    float nd = __ldg(&g_ndst[node]);
    acc.x *= nd; acc.y *= nd; acc.z *= nd; acc.w *= nd;
    out[(unsigned)node * DVEC + q] = acc;
}

extern "C" void kernel_launch(void* const* d_in, const int* in_sizes, int n_in,
                              void* d_out, int out_size) {
    const float4* feat = (const float4*)d_in[0];
    const int*    src  = (const int*)d_in[1];
    const int*    dst  = (const int*)d_in[2];
    float4*       out  = (float4*)d_out;

    int N = in_sizes[0] / DFEAT;   // 100000
    int E = in_sizes[1];           // 1000000

    // 1) zero scratch
    {
        int threads = 256;
        int blocks = (N + threads - 1) / threads;
        zero_kernel<<<blocks, threads>>>(N);
    }

    // 2) degree count + dst binning
    {
        int threads = 256;
        int blocks = (E + threads - 1) / threads;
        bin_kernel<<<blocks, threads>>>(src, dst, E);
    }

    // 3) per-node norms
    {
        int threads = 256;
        int blocks = (N + threads - 1) / threads;
        norm_kernel<<<blocks, threads>>>(N);
    }

    // 4) smem-staged gather, 16 nodes per block
    {
        int blocks = (N + NODES_PER_BLK - 1) / NODES_PER_BLK;
        gather_kernel<<<blocks, 256>>>(feat, out, N);
    }
}